// round 1
// baseline (speedup 1.0000x reference)
#include <cuda_runtime.h>

#define Dq 512
#define Hq 64
#define NMAX 40
#define EMAX 104
#define KC 128
#define BMAX 8192
#define NTHREADS 512

// ---------------- device scratch (fixed size, no allocation) ----------------
__device__ float g_M1[Dq * Hq];   // Wg @ W1
__device__ float g_M2[Dq * Hq];   // Wg @ W2
__device__ float g_M3a[Dq * Hq];  // Wg @ W3[:D]
__device__ float g_M3b[Dq * Hq];  // Wg @ W3[D:]
__device__ float g_c[Hq];         // bg@W1 + b1 + bg@W2 + b2
__device__ float g_d3[Hq];        // bg@W3[:D] + b3
__device__ float g_e3[Hq];        // bg@W3[D:]
__device__ int g_node_off[BMAX + 1];
__device__ int g_tok_off[BMAX + 1];

struct Smem {
    float xa[NMAX * Dq];   // node features (input / after hop2)
    float xb[NMAX * Dq];   // hop scratch; reused for staging M-matrix chunks
    float ws[NMAX * Hq];   // W[j][h] = p_act[j] @ M2
    float sP[Dq];
    float u[Hq];
    float af[NMAX];
    float dinv[NMAX];
    float adjw[EMAX];
    float outp[8 * Hq];
    int es[EMAX], ed[EMAX], adjs[EMAX];
    int csr[NMAX + 1];
    int deg[NMAX], cnt[NMAX], act[NMAX];
    int nact;
    float Atot;
};

// ---------------- session boundaries ----------------
__global__ void k_mark(const int* __restrict__ batch, int N) {
    int i = blockIdx.x * blockDim.x + threadIdx.x;
    if (i < N) {
        if (i == 0 || batch[i] != batch[i - 1]) g_node_off[batch[i]] = i;
    }
}

// exclusive scan of seq_len -> g_tok_off; also caps node_off
__global__ void k_scan(const int* __restrict__ seq_len, int B, int N) {
    __shared__ int wsum[32];
    __shared__ int carry_s;
    if (threadIdx.x == 0) { carry_s = 0; g_node_off[B] = N; }
    __syncthreads();
    for (int base = 0; base < B; base += 1024) {
        int i = base + (int)threadIdx.x;
        int v = (i < B) ? seq_len[i] : 0;
        int lane = threadIdx.x & 31, w = threadIdx.x >> 5;
        int x = v;
        for (int o = 1; o < 32; o <<= 1) {
            int y = __shfl_up_sync(0xffffffffu, x, o);
            if (lane >= o) x += y;
        }
        if (lane == 31) wsum[w] = x;
        __syncthreads();
        if (w == 0) {
            int s = wsum[lane];
            for (int o = 1; o < 32; o <<= 1) {
                int y = __shfl_up_sync(0xffffffffu, s, o);
                if (lane >= o) s += y;
            }
            wsum[lane] = s;
        }
        __syncthreads();
        int excl = x - v + (w ? wsum[w - 1] : 0) + carry_s;
        if (i < B) g_tok_off[i] = excl;
        __syncthreads();
        if (threadIdx.x == 0) carry_s = carry_s + wsum[31];
        __syncthreads();
    }
    if (threadIdx.x == 0) g_tok_off[B] = carry_s;
}

// ---------------- fused matrices: Wg @ {W1, W2, W3_top, W3_bot} ----------------
__global__ void k_mats(const float* __restrict__ Wg, const float* __restrict__ W1,
                       const float* __restrict__ W2, const float* __restrict__ W3) {
    __shared__ float wg8[8 * Dq];
    int kb = blockIdx.x;
    int m = blockIdx.y;
    const float* W;
    float* out;
    if (m == 0)      { W = W1;            out = g_M1; }
    else if (m == 1) { W = W2;            out = g_M2; }
    else if (m == 2) { W = W3;            out = g_M3a; }
    else             { W = W3 + Dq * Hq;  out = g_M3b; }
    for (int i = threadIdx.x; i < 8 * Dq; i += 256) wg8[i] = Wg[kb * 8 * Dq + i];
    __syncthreads();
    int h = threadIdx.x & 63;
    int r0 = threadIdx.x >> 6;  // 0..3 ; also handles r0+4
    float a0 = 0.f, a1 = 0.f;
    for (int d = 0; d < Dq; d++) {
        float wv = W[d * Hq + h];
        a0 += wg8[r0 * Dq + d] * wv;
        a1 += wg8[(r0 + 4) * Dq + d] * wv;
    }
    out[(kb * 8 + r0) * Hq + h] = a0;
    out[(kb * 8 + r0 + 4) * Hq + h] = a1;
}

__global__ void k_vecs(const float* __restrict__ bg, const float* __restrict__ b1,
                       const float* __restrict__ b2, const float* __restrict__ b3,
                       const float* __restrict__ W1, const float* __restrict__ W2,
                       const float* __restrict__ W3) {
    int h = threadIdx.x;
    float cv = b1[h] + b2[h], dv = b3[h], ev = 0.f;
    for (int d = 0; d < Dq; d++) {
        float bgv = bg[d];
        cv += bgv * (W1[d * Hq + h] + W2[d * Hq + h]);
        dv += bgv * W3[d * Hq + h];
        ev += bgv * W3[(Dq + d) * Hq + h];
    }
    g_c[h] = cv; g_d3[h] = dv; g_e3[h] = ev;
}

// ---------------- fused per-session kernel ----------------
__global__ void __launch_bounds__(NTHREADS, 1) k_main(
    const float* __restrict__ hidden, const float* __restrict__ Wq,
    const float* __restrict__ bq, const int* __restrict__ eidx,
    const int* __restrict__ sidx, const int* __restrict__ seq_len,
    float* __restrict__ out, int E, int B) {
    extern __shared__ unsigned char smraw[];
    Smem* S = (Smem*)smraw;
    int b = blockIdx.x, tid = threadIdx.x;
    int nbase = g_node_off[b];
    int nn = g_node_off[b + 1] - nbase;
    int eps = E / B;
    int ne = eps + nn;  // edges + self loops

    // 1) load session node features into smem
    {
        const float4* src = (const float4*)(hidden + (size_t)nbase * Dq);
        float4* dst = (float4*)S->xa;
        int cnt4 = nn * Dq / 4;
        for (int i = tid; i < cnt4; i += NTHREADS) dst[i] = src[i];
    }
    if (tid < NMAX) { S->deg[tid] = 0; S->cnt[tid] = 0; }
    // 2) edges (localized) + self loops
    for (int e = tid; e < ne; e += NTHREADS) {
        int s, d;
        if (e < eps) {
            s = eidx[(size_t)b * eps + e] - nbase;
            d = eidx[(size_t)E + (size_t)b * eps + e] - nbase;
        } else {
            s = d = e - eps;
        }
        S->es[e] = s; S->ed[e] = d;
    }
    __syncthreads();
    for (int e = tid; e < ne; e += NTHREADS) atomicAdd(&S->deg[S->ed[e]], 1);
    __syncthreads();
    if (tid < nn) S->dinv[tid] = rsqrtf((float)S->deg[tid]);
    if (tid == 0) {
        int acc = 0;
        for (int c2 = 0; c2 < nn; c2++) { S->csr[c2] = acc; acc += S->deg[c2]; }
        S->csr[nn] = acc;
    }
    __syncthreads();
    // deterministic CSR placement (rank among same-target edges by index)
    for (int e = tid; e < ne; e += NTHREADS) {
        int d = S->ed[e];
        int r = 0;
        for (int q = 0; q < e; q++) r += (S->ed[q] == d);
        int pos = S->csr[d] + r;
        S->adjs[pos] = S->es[e];
        S->adjw[pos] = S->dinv[S->es[e]] * S->dinv[d];
    }
    __syncthreads();
    // 3) two normalized-adjacency hops, fully in smem
    for (int hop = 0; hop < 2; hop++) {
        const float* xin = hop ? S->xb : S->xa;
        float* xout = hop ? S->xa : S->xb;
        int tot = nn * Dq;
        for (int idx = tid; idx < tot; idx += NTHREADS) {
            int c2 = idx >> 9, d0 = idx & (Dq - 1);
            float s = 0.f;
            int a0 = S->csr[c2], a1 = S->csr[c2 + 1];
            for (int a = a0; a < a1; a++) s += S->adjw[a] * xin[S->adjs[a] * Dq + d0];
            xout[idx] = s;
        }
        __syncthreads();
    }
    // p = S->xa now.

    // 4) token histogram + active node list
    int tbase = g_tok_off[b];
    int sl = seq_len[b];
    for (int t = tid; t < sl; t += NTHREADS) atomicAdd(&S->cnt[sidx[tbase + t]], 1);
    __syncthreads();
    int lastnode = sidx[tbase + sl - 1];
    if (tid == 0) {
        int na = 0;
        for (int n2 = 0; n2 < nn; n2++)
            if (S->cnt[n2] > 0) S->act[na++] = n2;
        S->nact = na;
    }
    __syncthreads();
    int nact = S->nact;
    int h = tid & (Hq - 1), jg = tid >> 6;  // 64 h-lanes x 8 node groups
    int lrow = lastnode * Dq;

    // 5) GEMM pass 1:  W[j] = p_act[j] @ M2  (and u = p_last @ M1 + c)
    float acc[5] = {0.f, 0.f, 0.f, 0.f, 0.f};
    float uacc = 0.f;
    int rowoff[5];
    bool valid[5];
#pragma unroll
    for (int i = 0; i < 5; i++) {
        int j = jg + 8 * i;
        valid[i] = (j < nact);
        rowoff[i] = valid[i] ? S->act[j] * Dq : 0;
    }
    for (int kc = 0; kc < Dq; kc += KC) {
        float* m2s = S->xb;
        float* m1s = S->xb + KC * Hq;
        {
            const float4* gM2p = (const float4*)(g_M2 + kc * Hq);
            const float4* gM1p = (const float4*)(g_M1 + kc * Hq);
            float4* s2 = (float4*)m2s;
            float4* s1 = (float4*)m1s;
            for (int i = tid; i < KC * Hq / 4; i += NTHREADS) {
                s2[i] = gM2p[i];
                s1[i] = gM1p[i];
            }
        }
        __syncthreads();
        for (int kk = 0; kk < KC; kk += 4) {
            float m0 = m2s[(kk + 0) * Hq + h], m1v = m2s[(kk + 1) * Hq + h];
            float m2v = m2s[(kk + 2) * Hq + h], m3v = m2s[(kk + 3) * Hq + h];
#pragma unroll
            for (int i = 0; i < 5; i++) {
                if (valid[i]) {
                    float4 a = *(const float4*)&S->xa[rowoff[i] + kc + kk];
                    acc[i] += a.x * m0 + a.y * m1v + a.z * m2v + a.w * m3v;
                }
            }
            if (jg == 0) {
                float4 a = *(const float4*)&S->xa[lrow + kc + kk];
                uacc += a.x * m1s[(kk + 0) * Hq + h] + a.y * m1s[(kk + 1) * Hq + h] +
                        a.z * m1s[(kk + 2) * Hq + h] + a.w * m1s[(kk + 3) * Hq + h];
            }
        }
        __syncthreads();
    }
#pragma unroll
    for (int i = 0; i < 5; i++)
        if (valid[i]) S->ws[(jg + 8 * i) * Hq + h] = acc[i];
    if (jg == 0) S->u[h] = uacc + g_c[h];
    __syncthreads();

    // 6) alpha per active node: a_n = cnt_n * (sigmoid(u + W[n]) @ Wq + bq)
    {
        int lane = tid & 31, w = tid >> 5;
        float bq0 = bq[0];
        float wql = Wq[lane], wqh = Wq[lane + 32];
        float ul = S->u[lane], uh = S->u[lane + 32];
        for (int j = w; j < nact; j += 16) {
            float x1 = ul + S->ws[j * Hq + lane];
            float x2 = uh + S->ws[j * Hq + lane + 32];
            float s = wql / (1.f + __expf(-x1)) + wqh / (1.f + __expf(-x2));
            for (int o = 16; o; o >>= 1) s += __shfl_xor_sync(0xffffffffu, s, o);
            if (lane == 0) S->af[j] = (s + bq0) * (float)S->cnt[S->act[j]];
        }
    }
    __syncthreads();
    if (tid == 0) {
        float A = 0.f;
        for (int j = 0; j < nact; j++) A += S->af[j];
        S->Atot = A;
    }
    // sP[k] = sum_j a_j * p_act[j][k]
    if (tid < Dq) {
        float s = 0.f;
        for (int j = 0; j < nact; j++) s += S->af[j] * S->xa[S->act[j] * Dq + tid];
        S->sP[tid] = s;
    }
    __syncthreads();

    // 7) pass 2: out = p_last@M3a + sP@M3b + d3 + A*e3
    float oacc = 0.f;
    int slice = tid >> 6;  // 8 k-slices of 16
    for (int kc = 0; kc < Dq; kc += KC) {
        float* m3as = S->xb;
        float* m3bs = S->xb + KC * Hq;
        {
            const float4* ga = (const float4*)(g_M3a + kc * Hq);
            const float4* gb = (const float4*)(g_M3b + kc * Hq);
            float4* sa = (float4*)m3as;
            float4* sb = (float4*)m3bs;
            for (int i = tid; i < KC * Hq / 4; i += NTHREADS) {
                sa[i] = ga[i];
                sb[i] = gb[i];
            }
        }
        __syncthreads();
#pragma unroll 4
        for (int kk = slice * 16; kk < slice * 16 + 16; kk++) {
            float pvv = S->xa[lrow + kc + kk];
            float spv = S->sP[kc + kk];
            oacc += pvv * m3as[kk * Hq + h] + spv * m3bs[kk * Hq + h];
        }
        __syncthreads();
    }
    S->outp[slice * Hq + h] = oacc;
    __syncthreads();
    if (tid < Hq) {
        float s = g_d3[tid] + S->Atot * g_e3[tid];
#pragma unroll
        for (int s2 = 0; s2 < 8; s2++) s += S->outp[s2 * Hq + tid];
        out[(size_t)b * Hq + tid] = s;
    }
}

// ---------------- launch ----------------
extern "C" void kernel_launch(void* const* d_in, const int* in_sizes, int n_in,
                              void* d_out, int out_size) {
    const float* hidden = (const float*)d_in[0];
    const float* Wg = (const float*)d_in[1];
    const float* bg = (const float*)d_in[2];
    const float* W1 = (const float*)d_in[3];
    const float* b1 = (const float*)d_in[4];
    const float* W2 = (const float*)d_in[5];
    const float* b2 = (const float*)d_in[6];
    const float* Wq = (const float*)d_in[7];
    const float* bq = (const float*)d_in[8];
    const float* W3 = (const float*)d_in[9];
    const float* b3 = (const float*)d_in[10];
    const int* eidx = (const int*)d_in[11];
    const int* batch = (const int*)d_in[12];
    const int* sidx = (const int*)d_in[13];
    const int* seql = (const int*)d_in[14];

    int N = in_sizes[0] / Dq;
    int B = in_sizes[14];
    int E = in_sizes[11] / 2;
    float* out = (float*)d_out;

    k_mark<<<(N + 255) / 256, 256>>>(batch, N);
    k_scan<<<1, 1024>>>(seql, B, N);
    dim3 gm(Dq / 8, 4);
    k_mats<<<gm, 256>>>(Wg, W1, W2, W3);
    k_vecs<<<1, Hq>>>(bg, b1, b2, b3, W1, W2, W3);

    cudaFuncSetAttribute(k_main, cudaFuncAttributeMaxDynamicSharedMemorySize,
                         (int)sizeof(Smem));
    k_main<<<B, NTHREADS, sizeof(Smem)>>>(hidden, Wq, bq, eidx, sidx, seql, out, E, B);
}

// round 2
// speedup vs baseline: 1.0008x; 1.0008x over previous
#include <cuda_runtime.h>

#define Dq 512
#define Hq 64
#define NMAX 40
#define EMAX 104
#define KC 128
#define BMAX 8192
#define NTHREADS 512

// ---------------- device scratch (fixed size, no allocation) ----------------
__device__ float g_M1[Dq * Hq];   // Wg @ W1
__device__ float g_M2[Dq * Hq];   // Wg @ W2
__device__ float g_M3a[Dq * Hq];  // Wg @ W3[:D]
__device__ float g_M3b[Dq * Hq];  // Wg @ W3[D:]
__device__ float g_c[Hq];         // bg@W1 + b1 + bg@W2 + b2
__device__ float g_d3[Hq];        // bg@W3[:D] + b3
__device__ float g_e3[Hq];        // bg@W3[D:]
__device__ int g_node_off[BMAX + 1];
__device__ int g_tok_off[BMAX + 1];

struct Smem {
    float xa[NMAX * Dq];   // node features (input / after hop2)
    float xb[NMAX * Dq];   // hop scratch; reused for staging M-matrix chunks
    float ws[NMAX * Hq];   // W[j][h] = p_act[j] @ M2
    float sP[Dq];
    float u[Hq];
    float af[NMAX];
    float dinv[NMAX];
    float adjw[EMAX];
    float outp[8 * Hq];
    int es[EMAX], ed[EMAX], adjs[EMAX];
    int csr[NMAX + 1];
    int deg[NMAX], cnt[NMAX], act[NMAX];
    int nact;
    float Atot;
};

// ---------------- session boundaries ----------------
__global__ void k_mark(const int* __restrict__ batch, int N) {
    int i = blockIdx.x * blockDim.x + threadIdx.x;
    if (i < N) {
        if (i == 0 || batch[i] != batch[i - 1]) g_node_off[batch[i]] = i;
    }
}

// exclusive scan of seq_len -> g_tok_off; also caps node_off
__global__ void k_scan(const int* __restrict__ seq_len, int B, int N) {
    __shared__ int wsum[32];
    __shared__ int carry_s;
    if (threadIdx.x == 0) { carry_s = 0; g_node_off[B] = N; }
    __syncthreads();
    for (int base = 0; base < B; base += 1024) {
        int i = base + (int)threadIdx.x;
        int v = (i < B) ? seq_len[i] : 0;
        int lane = threadIdx.x & 31, w = threadIdx.x >> 5;
        int x = v;
        for (int o = 1; o < 32; o <<= 1) {
            int y = __shfl_up_sync(0xffffffffu, x, o);
            if (lane >= o) x += y;
        }
        if (lane == 31) wsum[w] = x;
        __syncthreads();
        if (w == 0) {
            int s = wsum[lane];
            for (int o = 1; o < 32; o <<= 1) {
                int y = __shfl_up_sync(0xffffffffu, s, o);
                if (lane >= o) s += y;
            }
            wsum[lane] = s;
        }
        __syncthreads();
        int excl = x - v + (w ? wsum[w - 1] : 0) + carry_s;
        if (i < B) g_tok_off[i] = excl;
        __syncthreads();
        if (threadIdx.x == 0) carry_s = carry_s + wsum[31];
        __syncthreads();
    }
    if (threadIdx.x == 0) g_tok_off[B] = carry_s;
}

// ---------------- fused matrices: Wg @ {W1, W2, W3_top, W3_bot} ----------------
__global__ void k_mats(const float* __restrict__ Wg, const float* __restrict__ W1,
                       const float* __restrict__ W2, const float* __restrict__ W3) {
    __shared__ float wg8[8 * Dq];
    int kb = blockIdx.x;
    int m = blockIdx.y;
    const float* W;
    float* out;
    if (m == 0)      { W = W1;            out = g_M1; }
    else if (m == 1) { W = W2;            out = g_M2; }
    else if (m == 2) { W = W3;            out = g_M3a; }
    else             { W = W3 + Dq * Hq;  out = g_M3b; }
    for (int i = threadIdx.x; i < 8 * Dq; i += 256) wg8[i] = Wg[kb * 8 * Dq + i];
    __syncthreads();
    int h = threadIdx.x & 63;
    int r0 = threadIdx.x >> 6;  // 0..3 ; also handles r0+4
    float a0 = 0.f, a1 = 0.f;
    for (int d = 0; d < Dq; d++) {
        float wv = W[d * Hq + h];
        a0 += wg8[r0 * Dq + d] * wv;
        a1 += wg8[(r0 + 4) * Dq + d] * wv;
    }
    out[(kb * 8 + r0) * Hq + h] = a0;
    out[(kb * 8 + r0 + 4) * Hq + h] = a1;
}

__global__ void k_vecs(const float* __restrict__ bg, const float* __restrict__ b1,
                       const float* __restrict__ b2, const float* __restrict__ b3,
                       const float* __restrict__ W1, const float* __restrict__ W2,
                       const float* __restrict__ W3) {
    int h = threadIdx.x;
    float cv = b1[h] + b2[h], dv = b3[h], ev = 0.f;
    for (int d = 0; d < Dq; d++) {
        float bgv = bg[d];
        cv += bgv * (W1[d * Hq + h] + W2[d * Hq + h]);
        dv += bgv * W3[d * Hq + h];
        ev += bgv * W3[(Dq + d) * Hq + h];
    }
    g_c[h] = cv; g_d3[h] = dv; g_e3[h] = ev;
}

// ---------------- fused per-session kernel ----------------
__global__ void __launch_bounds__(NTHREADS, 1) k_main(
    const float* __restrict__ hidden, const float* __restrict__ Wq,
    const float* __restrict__ bq, const int* __restrict__ eidx,
    const int* __restrict__ sidx, const int* __restrict__ seq_len,
    float* __restrict__ out, int E, int B) {
    extern __shared__ unsigned char smraw[];
    Smem* S = (Smem*)smraw;
    int b = blockIdx.x, tid = threadIdx.x;
    int nbase = g_node_off[b];
    int nn = g_node_off[b + 1] - nbase;
    int eps = E / B;
    int ne = eps + nn;  // edges + self loops

    // 1) load session node features into smem
    {
        const float4* src = (const float4*)(hidden + (size_t)nbase * Dq);
        float4* dst = (float4*)S->xa;
        int cnt4 = nn * Dq / 4;
        for (int i = tid; i < cnt4; i += NTHREADS) dst[i] = src[i];
    }
    if (tid < NMAX) { S->deg[tid] = 0; S->cnt[tid] = 0; }
    // 2) edges (localized) + self loops
    for (int e = tid; e < ne; e += NTHREADS) {
        int s, d;
        if (e < eps) {
            s = eidx[(size_t)b * eps + e] - nbase;
            d = eidx[(size_t)E + (size_t)b * eps + e] - nbase;
        } else {
            s = d = e - eps;
        }
        S->es[e] = s; S->ed[e] = d;
    }
    __syncthreads();
    for (int e = tid; e < ne; e += NTHREADS) atomicAdd(&S->deg[S->ed[e]], 1);
    __syncthreads();
    if (tid < nn) S->dinv[tid] = rsqrtf((float)S->deg[tid]);
    if (tid == 0) {
        int acc = 0;
        for (int c2 = 0; c2 < nn; c2++) { S->csr[c2] = acc; acc += S->deg[c2]; }
        S->csr[nn] = acc;
    }
    __syncthreads();
    // deterministic CSR placement (rank among same-target edges by index)
    for (int e = tid; e < ne; e += NTHREADS) {
        int d = S->ed[e];
        int r = 0;
        for (int q = 0; q < e; q++) r += (S->ed[q] == d);
        int pos = S->csr[d] + r;
        S->adjs[pos] = S->es[e];
        S->adjw[pos] = S->dinv[S->es[e]] * S->dinv[d];
    }
    __syncthreads();
    // 3) two normalized-adjacency hops, fully in smem
    for (int hop = 0; hop < 2; hop++) {
        const float* xin = hop ? S->xb : S->xa;
        float* xout = hop ? S->xa : S->xb;
        int tot = nn * Dq;
        for (int idx = tid; idx < tot; idx += NTHREADS) {
            int c2 = idx >> 9, d0 = idx & (Dq - 1);
            float s = 0.f;
            int a0 = S->csr[c2], a1 = S->csr[c2 + 1];
            for (int a = a0; a < a1; a++) s += S->adjw[a] * xin[S->adjs[a] * Dq + d0];
            xout[idx] = s;
        }
        __syncthreads();
    }
    // p = S->xa now.

    // 4) token histogram + active node list
    int tbase = g_tok_off[b];
    int sl = seq_len[b];
    for (int t = tid; t < sl; t += NTHREADS) atomicAdd(&S->cnt[sidx[tbase + t]], 1);
    __syncthreads();
    int lastnode = sidx[tbase + sl - 1];
    if (tid == 0) {
        int na = 0;
        for (int n2 = 0; n2 < nn; n2++)
            if (S->cnt[n2] > 0) S->act[na++] = n2;
        S->nact = na;
    }
    __syncthreads();
    int nact = S->nact;
    int h = tid & (Hq - 1), jg = tid >> 6;  // 64 h-lanes x 8 node groups
    int lrow = lastnode * Dq;

    // 5) GEMM pass 1:  W[j] = p_act[j] @ M2  (and u = p_last @ M1 + c)
    float acc[5] = {0.f, 0.f, 0.f, 0.f, 0.f};
    float uacc = 0.f;
    int rowoff[5];
    bool valid[5];
#pragma unroll
    for (int i = 0; i < 5; i++) {
        int j = jg + 8 * i;
        valid[i] = (j < nact);
        rowoff[i] = valid[i] ? S->act[j] * Dq : 0;
    }
    for (int kc = 0; kc < Dq; kc += KC) {
        float* m2s = S->xb;
        float* m1s = S->xb + KC * Hq;
        {
            const float4* gM2p = (const float4*)(g_M2 + kc * Hq);
            const float4* gM1p = (const float4*)(g_M1 + kc * Hq);
            float4* s2 = (float4*)m2s;
            float4* s1 = (float4*)m1s;
            for (int i = tid; i < KC * Hq / 4; i += NTHREADS) {
                s2[i] = gM2p[i];
                s1[i] = gM1p[i];
            }
        }
        __syncthreads();
        for (int kk = 0; kk < KC; kk += 4) {
            float m0 = m2s[(kk + 0) * Hq + h], m1v = m2s[(kk + 1) * Hq + h];
            float m2v = m2s[(kk + 2) * Hq + h], m3v = m2s[(kk + 3) * Hq + h];
#pragma unroll
            for (int i = 0; i < 5; i++) {
                if (valid[i]) {
                    float4 a = *(const float4*)&S->xa[rowoff[i] + kc + kk];
                    acc[i] += a.x * m0 + a.y * m1v + a.z * m2v + a.w * m3v;
                }
            }
            if (jg == 0) {
                float4 a = *(const float4*)&S->xa[lrow + kc + kk];
                uacc += a.x * m1s[(kk + 0) * Hq + h] + a.y * m1s[(kk + 1) * Hq + h] +
                        a.z * m1s[(kk + 2) * Hq + h] + a.w * m1s[(kk + 3) * Hq + h];
            }
        }
        __syncthreads();
    }
#pragma unroll
    for (int i = 0; i < 5; i++)
        if (valid[i]) S->ws[(jg + 8 * i) * Hq + h] = acc[i];
    if (jg == 0) S->u[h] = uacc + g_c[h];
    __syncthreads();

    // 6) alpha per active node: a_n = cnt_n * (sigmoid(u + W[n]) @ Wq + bq)
    {
        int lane = tid & 31, w = tid >> 5;
        float bq0 = bq[0];
        float wql = Wq[lane], wqh = Wq[lane + 32];
        float ul = S->u[lane], uh = S->u[lane + 32];
        for (int j = w; j < nact; j += 16) {
            float x1 = ul + S->ws[j * Hq + lane];
            float x2 = uh + S->ws[j * Hq + lane + 32];
            float s = wql / (1.f + __expf(-x1)) + wqh / (1.f + __expf(-x2));
            for (int o = 16; o; o >>= 1) s += __shfl_xor_sync(0xffffffffu, s, o);
            if (lane == 0) S->af[j] = (s + bq0) * (float)S->cnt[S->act[j]];
        }
    }
    __syncthreads();
    if (tid == 0) {
        float A = 0.f;
        for (int j = 0; j < nact; j++) A += S->af[j];
        S->Atot = A;
    }
    // sP[k] = sum_j a_j * p_act[j][k]
    if (tid < Dq) {
        float s = 0.f;
        for (int j = 0; j < nact; j++) s += S->af[j] * S->xa[S->act[j] * Dq + tid];
        S->sP[tid] = s;
    }
    __syncthreads();

    // 7) pass 2: out = p_last@M3a + sP@M3b + d3 + A*e3
    float oacc = 0.f;
    int slice = tid >> 6;  // 8 k-slices of 16
    for (int kc = 0; kc < Dq; kc += KC) {
        float* m3as = S->xb;
        float* m3bs = S->xb + KC * Hq;
        {
            const float4* ga = (const float4*)(g_M3a + kc * Hq);
            const float4* gb = (const float4*)(g_M3b + kc * Hq);
            float4* sa = (float4*)m3as;
            float4* sb = (float4*)m3bs;
            for (int i = tid; i < KC * Hq / 4; i += NTHREADS) {
                sa[i] = ga[i];
                sb[i] = gb[i];
            }
        }
        __syncthreads();
#pragma unroll 4
        for (int kk = slice * 16; kk < slice * 16 + 16; kk++) {
            float pvv = S->xa[lrow + kc + kk];
            float spv = S->sP[kc + kk];
            oacc += pvv * m3as[kk * Hq + h] + spv * m3bs[kk * Hq + h];
        }
        __syncthreads();
    }
    S->outp[slice * Hq + h] = oacc;
    __syncthreads();
    if (tid < Hq) {
        float s = g_d3[tid] + S->Atot * g_e3[tid];
#pragma unroll
        for (int s2 = 0; s2 < 8; s2++) s += S->outp[s2 * Hq + tid];
        out[(size_t)b * Hq + tid] = s;
    }
}

// ---------------- launch ----------------
extern "C" void kernel_launch(void* const* d_in, const int* in_sizes, int n_in,
                              void* d_out, int out_size) {
    const float* hidden = (const float*)d_in[0];
    const float* Wg = (const float*)d_in[1];
    const float* bg = (const float*)d_in[2];
    const float* W1 = (const float*)d_in[3];
    const float* b1 = (const float*)d_in[4];
    const float* W2 = (const float*)d_in[5];
    const float* b2 = (const float*)d_in[6];
    const float* Wq = (const float*)d_in[7];
    const float* bq = (const float*)d_in[8];
    const float* W3 = (const float*)d_in[9];
    const float* b3 = (const float*)d_in[10];
    const int* eidx = (const int*)d_in[11];
    const int* batch = (const int*)d_in[12];
    const int* sidx = (const int*)d_in[13];
    const int* seql = (const int*)d_in[14];

    int N = in_sizes[0] / Dq;
    int B = in_sizes[14];
    int E = in_sizes[11] / 2;
    float* out = (float*)d_out;

    k_mark<<<(N + 255) / 256, 256>>>(batch, N);
    k_scan<<<1, 1024>>>(seql, B, N);
    dim3 gm(Dq / 8, 4);
    k_mats<<<gm, 256>>>(Wg, W1, W2, W3);
    k_vecs<<<1, Hq>>>(bg, b1, b2, b3, W1, W2, W3);

    cudaFuncSetAttribute(k_main, cudaFuncAttributeMaxDynamicSharedMemorySize,
                         (int)sizeof(Smem));
    k_main<<<B, NTHREADS, sizeof(Smem)>>>(hidden, Wq, bq, eidx, sidx, seql, out, E, B);
}

// round 4
// speedup vs baseline: 1.4225x; 1.4213x over previous
#include <cuda_runtime.h>

#define Dq 512
#define Hq 64
#define NMAX 40
#define EMAX 104
#define BMAX 8192
#define J 50
#define NTHREADS 512

typedef unsigned long long ull;

// ---------------- device scratch ----------------
__device__ float g_M1[Dq * Hq];
__device__ float g_M2[Dq * Hq];
__device__ float g_M3T[Hq * 1040];   // [h][k] k<1024, stride 1040
__device__ float g_c[Hq];
__device__ float g_d3[Hq];
__device__ float g_e3[Hq];
__device__ float g_VS[BMAX * 1024];  // [p_last(512), sP(512)] per session
__device__ float g_A[BMAX];
__device__ int g_node_off[BMAX + 1];
__device__ int g_tok_off[BMAX + 1];

__device__ __forceinline__ void ffma2(ull& a, ull x, ull y) {
    asm("fma.rn.f32x2 %0, %1, %2, %0;" : "+l"(a) : "l"(x), "l"(y));
}
__device__ __forceinline__ ull splat2(float v) {
    ull r; asm("mov.b64 %0, {%1, %1};" : "=l"(r) : "f"(v)); return r;
}
__device__ __forceinline__ float2 unpk(ull v) {
    float2 r; asm("mov.b64 {%0, %1}, %2;" : "=f"(r.x), "=f"(r.y) : "l"(v)); return r;
}

struct SmemM {
    float pt[Dq * J];      // transposed compact p (also initial row-major xa)
    float xb[NMAX * Dq];   // hop scratch / M chunk staging
    float ws[48 * Hq];
    float u[Hq];
    float af[48];
    float dinv[48];
    float adjw[EMAX];
    int es[EMAX], ed[EMAX], adjs[EMAX];
    int csr[49];
    int deg[48], cnt[48], act[48];
    int nact, jlast;
};

// ---------------- prelude ----------------
__global__ void k_mark(const int* __restrict__ batch, int N) {
    int i = blockIdx.x * blockDim.x + threadIdx.x;
    if (i < N) {
        if (i == 0 || batch[i] != batch[i - 1]) g_node_off[batch[i]] = i;
    }
}

__global__ void k_scan(const int* __restrict__ seq_len, int B, int N) {
    __shared__ int wsum[32];
    __shared__ int carry_s;
    if (threadIdx.x == 0) { carry_s = 0; g_node_off[B] = N; }
    __syncthreads();
    for (int base = 0; base < B; base += 1024) {
        int i = base + (int)threadIdx.x;
        int v = (i < B) ? seq_len[i] : 0;
        int lane = threadIdx.x & 31, w = threadIdx.x >> 5;
        int x = v;
        for (int o = 1; o < 32; o <<= 1) {
            int y = __shfl_up_sync(0xffffffffu, x, o);
            if (lane >= o) x += y;
        }
        if (lane == 31) wsum[w] = x;
        __syncthreads();
        if (w == 0) {
            int s = wsum[lane];
            for (int o = 1; o < 32; o <<= 1) {
                int y = __shfl_up_sync(0xffffffffu, s, o);
                if (lane >= o) s += y;
            }
            wsum[lane] = s;
        }
        __syncthreads();
        int excl = x - v + (w ? wsum[w - 1] : 0) + carry_s;
        if (i < B) g_tok_off[i] = excl;
        __syncthreads();
        if (threadIdx.x == 0) carry_s = carry_s + wsum[31];
        __syncthreads();
    }
    if (threadIdx.x == 0) g_tok_off[B] = carry_s;
}

__global__ void k_mats(const float* __restrict__ Wg, const float* __restrict__ W1,
                       const float* __restrict__ W2, const float* __restrict__ W3) {
    __shared__ float wg8[8 * Dq];
    int kb = blockIdx.x;
    int m = blockIdx.y;
    const float* W;
    if (m == 0)      W = W1;
    else if (m == 1) W = W2;
    else if (m == 2) W = W3;
    else             W = W3 + Dq * Hq;
    for (int i = threadIdx.x; i < 8 * Dq; i += 256) wg8[i] = Wg[kb * 8 * Dq + i];
    __syncthreads();
    int h = threadIdx.x & 63;
    int r0 = threadIdx.x >> 6;
    float a0 = 0.f, a1 = 0.f;
    for (int d = 0; d < Dq; d++) {
        float wv = W[d * Hq + h];
        a0 += wg8[r0 * Dq + d] * wv;
        a1 += wg8[(r0 + 4) * Dq + d] * wv;
    }
    int row0 = kb * 8 + r0, row1 = kb * 8 + r0 + 4;
    if (m == 0)      { g_M1[row0 * Hq + h] = a0; g_M1[row1 * Hq + h] = a1; }
    else if (m == 1) { g_M2[row0 * Hq + h] = a0; g_M2[row1 * Hq + h] = a1; }
    else {
        int off = (m == 3) ? 512 : 0;
        g_M3T[h * 1040 + off + row0] = a0;
        g_M3T[h * 1040 + off + row1] = a1;
    }
}

__global__ void k_vecs(const float* __restrict__ bg, const float* __restrict__ b1,
                       const float* __restrict__ b2, const float* __restrict__ b3,
                       const float* __restrict__ W1, const float* __restrict__ W2,
                       const float* __restrict__ W3) {
    __shared__ float red[3][128];
    int h = blockIdx.x, t = threadIdx.x;
    float cv = 0.f, dv = 0.f, ev = 0.f;
    for (int d = t; d < Dq; d += 128) {
        float bgv = bg[d];
        cv += bgv * (W1[d * Hq + h] + W2[d * Hq + h]);
        dv += bgv * W3[d * Hq + h];
        ev += bgv * W3[(Dq + d) * Hq + h];
    }
    red[0][t] = cv; red[1][t] = dv; red[2][t] = ev;
    __syncthreads();
    for (int s = 64; s; s >>= 1) {
        if (t < s) {
            red[0][t] += red[0][t + s];
            red[1][t] += red[1][t + s];
            red[2][t] += red[2][t + s];
        }
        __syncthreads();
    }
    if (t == 0) {
        g_c[h] = red[0][0] + b1[h] + b2[h];
        g_d3[h] = red[1][0] + b3[h];
        g_e3[h] = red[2][0];
    }
}

// ---------------- per-session fused kernel ----------------
__global__ void __launch_bounds__(NTHREADS, 1) k_main(
    const float* __restrict__ hidden, const float* __restrict__ Wq,
    const float* __restrict__ bq, const int* __restrict__ eidx,
    const int* __restrict__ sidx, const int* __restrict__ seq_len,
    int E, int B) {
    extern __shared__ unsigned char smraw[];
    SmemM* S = (SmemM*)smraw;
    int b = blockIdx.x, tid = threadIdx.x;
    int nbase = g_node_off[b];
    int nn = g_node_off[b + 1] - nbase;
    int eps = E / B;
    int ne = eps + nn;

    if (tid < 48) { S->deg[tid] = 0; S->cnt[tid] = 0; }
    // load session node features row-major into pt region
    {
        const float4* src = (const float4*)(hidden + (size_t)nbase * Dq);
        float4* dst = (float4*)S->pt;
        int cnt4 = nn * (Dq / 4);
        for (int i = tid; i < cnt4; i += NTHREADS) dst[i] = src[i];
    }
    for (int e = tid; e < ne; e += NTHREADS) {
        int s, d;
        if (e < eps) {
            s = eidx[(size_t)b * eps + e] - nbase;
            d = eidx[(size_t)E + (size_t)b * eps + e] - nbase;
        } else {
            s = d = e - eps;
        }
        S->es[e] = s; S->ed[e] = d;
    }
    __syncthreads();
    for (int e = tid; e < ne; e += NTHREADS) atomicAdd(&S->deg[S->ed[e]], 1);
    int tbase = g_tok_off[b];
    int sl = seq_len[b];
    for (int t = tid; t < sl; t += NTHREADS) atomicAdd(&S->cnt[sidx[tbase + t]], 1);
    __syncthreads();
    if (tid < nn) S->dinv[tid] = rsqrtf((float)S->deg[tid]);
    if (tid == 0) {
        int acc = 0;
        for (int c2 = 0; c2 < nn; c2++) { S->csr[c2] = acc; acc += S->deg[c2]; }
        S->csr[nn] = acc;
    }
    if (tid == 32) {
        int lastnode = sidx[tbase + sl - 1];
        int na = 0, jl = 0;
        for (int n2 = 0; n2 < nn; n2++)
            if (S->cnt[n2] > 0) {
                if (n2 == lastnode) jl = na;
                S->act[na++] = n2;
            }
        S->nact = na;
        S->jlast = jl;
    }
    __syncthreads();
    // deterministic CSR fill
    for (int e = tid; e < ne; e += NTHREADS) {
        int d = S->ed[e];
        int r = 0;
        for (int q = 0; q < e; q++) r += (S->ed[q] == d);
        int pos = S->csr[d] + r;
        S->adjs[pos] = S->es[e];
        S->adjw[pos] = S->dinv[S->es[e]] * S->dinv[d];
    }
    __syncthreads();
    // hop1: pt(row-major) -> xb
    {
        int tot = nn * Dq;
        for (int idx = tid; idx < tot; idx += NTHREADS) {
            int row = idx >> 9, d0 = idx & (Dq - 1);
            float s = 0.f;
            int a0 = S->csr[row], a1 = S->csr[row + 1];
            for (int a = a0; a < a1; a++) s += S->adjw[a] * S->pt[S->adjs[a] * Dq + d0];
            S->xb[idx] = s;
        }
    }
    __syncthreads();
    int nact = S->nact;
    int jlast = S->jlast;
    // hop2: xb -> pt transposed compact over active nodes
    {
        int tot = nact * Dq;
        for (int idx = tid; idx < tot; idx += NTHREADS) {
            int j = idx >> 9, d0 = idx & (Dq - 1);
            int row = S->act[j];
            float s = 0.f;
            int a0 = S->csr[row], a1 = S->csr[row + 1];
            for (int a = a0; a < a1; a++) s += S->adjw[a] * S->xb[S->adjs[a] * Dq + d0];
            S->pt[d0 * J + j] = s;
        }
    }
    __syncthreads();

    // GEMM: ws[j][h] = p_act[j]@M2 ;  u[h] = p_last@M1 + c[h]
    int ht = tid & 15;
    int ks = (tid >> 4) & 3;
    int jt = tid >> 6;
    int jb = jt * 6;
    bool jact = (jb < nact);
    bool dou = (jt == 7);   // j 42..47 never active (nact<=40): dedicate to u
    ull acc[3][4];
#pragma unroll
    for (int p = 0; p < 3; p++)
#pragma unroll
        for (int hh = 0; hh < 4; hh++) acc[p][hh] = 0ull;
    float ua[4] = {0.f, 0.f, 0.f, 0.f};
    float* m2s = S->xb;
    float* m1s = S->xb + 4096;
    int kl = ks * 16;
    for (int ch = 0; ch < 8; ch++) {
        {
            const float4* gm2 = (const float4*)(g_M2 + ch * 64 * Hq);
            const float4* gm1 = (const float4*)(g_M1 + ch * 64 * Hq);
            float4* s2 = (float4*)m2s;
            float4* s1 = (float4*)m1s;
            for (int i = tid; i < 1024; i += NTHREADS) { s2[i] = gm2[i]; s1[i] = gm1[i]; }
        }
        __syncthreads();
        if (jact) {
#pragma unroll 4
            for (int s = 0; s < 16; s++) {
                const float* prow = S->pt + (ch * 64 + kl + s) * J;
                float4 mv = *(const float4*)(m2s + (kl + s) * Hq + ht * 4);
                ull r0 = *(const ull*)(prow + jb);
                ull r1 = *(const ull*)(prow + jb + 2);
                ull r2 = *(const ull*)(prow + jb + 4);
                ull s0 = splat2(mv.x), s1 = splat2(mv.y);
                ull s2 = splat2(mv.z), s3 = splat2(mv.w);
                ffma2(acc[0][0], r0, s0); ffma2(acc[1][0], r1, s0); ffma2(acc[2][0], r2, s0);
                ffma2(acc[0][1], r0, s1); ffma2(acc[1][1], r1, s1); ffma2(acc[2][1], r2, s1);
                ffma2(acc[0][2], r0, s2); ffma2(acc[1][2], r1, s2); ffma2(acc[2][2], r2, s2);
                ffma2(acc[0][3], r0, s3); ffma2(acc[1][3], r1, s3); ffma2(acc[2][3], r2, s3);
            }
        } else if (dou) {
#pragma unroll 4
            for (int s = 0; s < 16; s++) {
                const float* prow = S->pt + (ch * 64 + kl + s) * J;
                float rl = prow[jlast];
                float4 w1 = *(const float4*)(m1s + (kl + s) * Hq + ht * 4);
                ua[0] += rl * w1.x; ua[1] += rl * w1.y;
                ua[2] += rl * w1.z; ua[3] += rl * w1.w;
            }
        }
        __syncthreads();
    }
    // deterministic k-slice reduction
    for (int r = 0; r < 4; r++) {
        if (ks == r) {
            if (jact) {
#pragma unroll
                for (int p = 0; p < 3; p++) {
                    int j0 = jb + 2 * p;
#pragma unroll
                    for (int hh = 0; hh < 4; hh++) {
                        float2 v = unpk(acc[p][hh]);
                        int h = ht * 4 + hh;
                        if (r == 0) {
                            S->ws[j0 * Hq + h] = v.x;
                            S->ws[(j0 + 1) * Hq + h] = v.y;
                        } else {
                            S->ws[j0 * Hq + h] += v.x;
                            S->ws[(j0 + 1) * Hq + h] += v.y;
                        }
                    }
                }
            } else if (dou) {
#pragma unroll
                for (int hh = 0; hh < 4; hh++) {
                    int h = ht * 4 + hh;
                    if (r == 0) S->u[h] = ua[hh] + g_c[h];
                    else S->u[h] += ua[hh];
                }
            }
        }
        __syncthreads();
    }

    // alpha per active node
    {
        int lane = tid & 31, w = tid >> 5;
        float bq0 = bq[0];
        float wql = Wq[lane], wqh = Wq[lane + 32];
        float ul = S->u[lane], uh = S->u[lane + 32];
        for (int j = w; j < nact; j += 16) {
            float x1 = ul + S->ws[j * Hq + lane];
            float x2 = uh + S->ws[j * Hq + lane + 32];
            float s = wql / (1.f + __expf(-x1)) + wqh / (1.f + __expf(-x2));
            for (int o = 16; o; o >>= 1) s += __shfl_xor_sync(0xffffffffu, s, o);
            if (lane == 0) S->af[j] = (s + bq0) * (float)S->cnt[S->act[j]];
        }
    }
    __syncthreads();
    if (tid == 0) {
        float A = 0.f;
        for (int j = 0; j < nact; j++) A += S->af[j];
        g_A[b] = A;
    }
    // write v_n (= p_last) and sP to g_VS
    if (tid < Dq) {
        float s = 0.f;
        for (int j = 0; j < nact; j++) s += S->af[j] * S->pt[tid * J + j];
        g_VS[(size_t)b * 1024 + tid] = S->pt[tid * J + jlast];
        g_VS[(size_t)b * 1024 + 512 + tid] = s;
    }
}

// ---------------- final matvec: out = VS @ M3 + d3 + A*e3 ----------------
#define FB 16
#define MS 132
__global__ void __launch_bounds__(256) k_final(float* __restrict__ out, int B) {
    extern __shared__ float fsm[];
    float* vs = fsm;               // FB * 1024
    float* mch = fsm + FB * 1024;  // 64 * MS
    int sb = blockIdx.x * FB;
    int tid = threadIdx.x;
    {
        const float4* src = (const float4*)(g_VS + (size_t)sb * 1024);
        float4* dst = (float4*)vs;
        for (int i = tid; i < FB * 256; i += 256) dst[i] = src[i];
    }
    int h = tid & 63, sg = tid >> 6;
    float acc[4] = {0.f, 0.f, 0.f, 0.f};
    const float* vsr0 = vs + (sg * 4 + 0) * 1024;
    const float* vsr1 = vs + (sg * 4 + 1) * 1024;
    const float* vsr2 = vs + (sg * 4 + 2) * 1024;
    const float* vsr3 = vs + (sg * 4 + 3) * 1024;
    for (int kc = 0; kc < 1024; kc += 128) {
        __syncthreads();
        for (int i = tid; i < 64 * 32; i += 256) {
            int r = i >> 5, c = i & 31;
            float4 v = *(const float4*)(g_M3T + r * 1040 + kc + c * 4);
            *(float4*)(mch + r * MS + c * 4) = v;
        }
        __syncthreads();
#pragma unroll 8
        for (int kk = 0; kk < 128; kk += 4) {
            float4 m = *(const float4*)(mch + h * MS + kk);
            float4 a0 = *(const float4*)(vsr0 + kc + kk);
            float4 a1 = *(const float4*)(vsr1 + kc + kk);
            float4 a2 = *(const float4*)(vsr2 + kc + kk);
            float4 a3 = *(const float4*)(vsr3 + kc + kk);
            acc[0] += a0.x * m.x + a0.y * m.y + a0.z * m.z + a0.w * m.w;
            acc[1] += a1.x * m.x + a1.y * m.y + a1.z * m.z + a1.w * m.w;
            acc[2] += a2.x * m.x + a2.y * m.y + a2.z * m.z + a2.w * m.w;
            acc[3] += a3.x * m.x + a3.y * m.y + a3.z * m.z + a3.w * m.w;
        }
    }
    float d3 = g_d3[h], e3 = g_e3[h];
#pragma unroll
    for (int i = 0; i < 4; i++) {
        int b = sb + sg * 4 + i;
        if (b < B) out[(size_t)b * Hq + h] = acc[i] + d3 + g_A[b] * e3;
    }
}

// ---------------- launch ----------------
extern "C" void kernel_launch(void* const* d_in, const int* in_sizes, int n_in,
                              void* d_out, int out_size) {
    const float* hidden = (const float*)d_in[0];
    const float* Wg = (const float*)d_in[1];
    const float* bg = (const float*)d_in[2];
    const float* W1 = (const float*)d_in[3];
    const float* b1 = (const float*)d_in[4];
    const float* W2 = (const float*)d_in[5];
    const float* b2 = (const float*)d_in[6];
    const float* Wq = (const float*)d_in[7];
    const float* bq = (const float*)d_in[8];
    const float* W3 = (const float*)d_in[9];
    const float* b3 = (const float*)d_in[10];
    const int* eidx = (const int*)d_in[11];
    const int* batch = (const int*)d_in[12];
    const int* sidx = (const int*)d_in[13];
    const int* seql = (const int*)d_in[14];

    int N = in_sizes[0] / Dq;
    int B = in_sizes[14];
    int E = in_sizes[11] / 2;
    float* out = (float*)d_out;

    k_mark<<<(N + 255) / 256, 256>>>(batch, N);
    k_scan<<<1, 1024>>>(seql, B, N);
    dim3 gm(Dq / 8, 4);
    k_mats<<<gm, 256>>>(Wg, W1, W2, W3);
    k_vecs<<<Hq, 128>>>(bg, b1, b2, b3, W1, W2, W3);

    cudaFuncSetAttribute(k_main, cudaFuncAttributeMaxDynamicSharedMemorySize,
                         (int)sizeof(SmemM));
    k_main<<<B, NTHREADS, sizeof(SmemM)>>>(hidden, Wq, bq, eidx, sidx, seql, E, B);

    int fsmem = (FB * 1024 + 64 * MS) * (int)sizeof(float);
    cudaFuncSetAttribute(k_final, cudaFuncAttributeMaxDynamicSharedMemorySize, fsmem);
    k_final<<<(B + FB - 1) / FB, 256, fsmem>>>(out, B);
}

// round 5
// speedup vs baseline: 2.4007x; 1.6876x over previous
#include <cuda_runtime.h>

#define Dq 512
#define Hq 64
#define NN 40
#define EMAX 104
#define BMAX 8192
#define NTHREADS 512

typedef unsigned long long ull;

// ---------------- device scratch ----------------
__device__ float g_M1[Dq * Hq];      // Wg@W1   [k][h]
__device__ float g_M2[Dq * Hq];      // Wg@W2   [k][h]
__device__ float g_M3T[Hq * 1040];   // [h][k] k<1024, stride 1040
__device__ float g_c[Hq];
__device__ float g_d3[Hq];
__device__ float g_e3[Hq];
__device__ float g_VS[BMAX * 1024];  // [v_n(512), sP(512)]
__device__ float g_A[BMAX];
__device__ int g_node_off[BMAX + 1];
__device__ int g_tok_off[BMAX + 1];

__device__ __forceinline__ void ffma2(ull& a, ull x, ull y) {
    asm("fma.rn.f32x2 %0, %1, %2, %0;" : "+l"(a) : "l"(x), "l"(y));
}
__device__ __forceinline__ ull splat2(float v) {
    ull r; asm("mov.b64 %0, {%1, %1};" : "=l"(r) : "f"(v)); return r;
}
__device__ __forceinline__ float2 unpk(ull v) {
    float2 r; asm("mov.b64 {%0, %1}, %2;" : "=f"(r.x), "=f"(r.y) : "l"(v)); return r;
}

struct __align__(16) SmemM {
    float X[NN * Dq];      // 81920B node features
    float R[2176];         // 8704B union: M2 stage[32*68] | A[40*48] | upart[512] | sP[512]
    float A2[NN * 48];     // 7680B  A2act rows (act-indexed), cols = raw node
    float Y[NN * Hq];      // 10240B
    float z[Dq];           // 2048B  (= v_n)
    float u[Hq];
    float ew[EMAX];
    float dinv[NN];
    float af[NN];
    float w[NN];
    int es[EMAX], ed[EMAX];
    int deg[NN], cnt[NN], act[NN];
    int nact, jlast, lastnode;
};

// ---------------- prelude ----------------
__global__ void k_mark(const int* __restrict__ batch, int N) {
    int i = blockIdx.x * blockDim.x + threadIdx.x;
    if (i < N) {
        if (i == 0 || batch[i] != batch[i - 1]) g_node_off[batch[i]] = i;
    }
}

__global__ void k_scan(const int* __restrict__ seq_len, int B, int N) {
    __shared__ int wsum[32];
    __shared__ int carry_s;
    if (threadIdx.x == 0) { carry_s = 0; g_node_off[B] = N; }
    __syncthreads();
    for (int base = 0; base < B; base += 1024) {
        int i = base + (int)threadIdx.x;
        int v = (i < B) ? seq_len[i] : 0;
        int lane = threadIdx.x & 31, w = threadIdx.x >> 5;
        int x = v;
        for (int o = 1; o < 32; o <<= 1) {
            int y = __shfl_up_sync(0xffffffffu, x, o);
            if (lane >= o) x += y;
        }
        if (lane == 31) wsum[w] = x;
        __syncthreads();
        if (w == 0) {
            int s = wsum[lane];
            for (int o = 1; o < 32; o <<= 1) {
                int y = __shfl_up_sync(0xffffffffu, s, o);
                if (lane >= o) s += y;
            }
            wsum[lane] = s;
        }
        __syncthreads();
        int excl = x - v + (w ? wsum[w - 1] : 0) + carry_s;
        if (i < B) g_tok_off[i] = excl;
        __syncthreads();
        if (threadIdx.x == 0) carry_s = carry_s + wsum[31];
        __syncthreads();
    }
    if (threadIdx.x == 0) g_tok_off[B] = carry_s;
}

__global__ void k_mats(const float* __restrict__ Wg, const float* __restrict__ W1,
                       const float* __restrict__ W2, const float* __restrict__ W3) {
    __shared__ float wg8[8 * Dq];
    int kb = blockIdx.x;
    int m = blockIdx.y;
    const float* W;
    if (m == 0)      W = W1;
    else if (m == 1) W = W2;
    else if (m == 2) W = W3;
    else             W = W3 + Dq * Hq;
    for (int i = threadIdx.x; i < 8 * Dq; i += 256) wg8[i] = Wg[kb * 8 * Dq + i];
    __syncthreads();
    int h = threadIdx.x & 63;
    int r0 = threadIdx.x >> 6;
    float a0 = 0.f, a1 = 0.f;
    for (int d = 0; d < Dq; d++) {
        float wv = W[d * Hq + h];
        a0 += wg8[r0 * Dq + d] * wv;
        a1 += wg8[(r0 + 4) * Dq + d] * wv;
    }
    int row0 = kb * 8 + r0, row1 = kb * 8 + r0 + 4;
    if (m == 0)      { g_M1[row0 * Hq + h] = a0; g_M1[row1 * Hq + h] = a1; }
    else if (m == 1) { g_M2[row0 * Hq + h] = a0; g_M2[row1 * Hq + h] = a1; }
    else {
        int off = (m == 3) ? 512 : 0;
        g_M3T[h * 1040 + off + row0] = a0;
        g_M3T[h * 1040 + off + row1] = a1;
    }
}

__global__ void k_vecs(const float* __restrict__ bg, const float* __restrict__ b1,
                       const float* __restrict__ b2, const float* __restrict__ b3,
                       const float* __restrict__ W1, const float* __restrict__ W2,
                       const float* __restrict__ W3) {
    __shared__ float red[3][128];
    int h = blockIdx.x, t = threadIdx.x;
    float cv = 0.f, dv = 0.f, ev = 0.f;
    for (int d = t; d < Dq; d += 128) {
        float bgv = bg[d];
        cv += bgv * (W1[d * Hq + h] + W2[d * Hq + h]);
        dv += bgv * W3[d * Hq + h];
        ev += bgv * W3[(Dq + d) * Hq + h];
    }
    red[0][t] = cv; red[1][t] = dv; red[2][t] = ev;
    __syncthreads();
    for (int s = 64; s; s >>= 1) {
        if (t < s) {
            red[0][t] += red[0][t + s];
            red[1][t] += red[1][t + s];
            red[2][t] += red[2][t + s];
        }
        __syncthreads();
    }
    if (t == 0) {
        g_c[h] = red[0][0] + b1[h] + b2[h];
        g_d3[h] = red[1][0] + b3[h];
        g_e3[h] = red[2][0];
    }
}

// ---------------- per-session fused kernel ----------------
__global__ void __launch_bounds__(NTHREADS, 2) k_main(
    const float* __restrict__ hidden, const float* __restrict__ Wq,
    const float* __restrict__ bq, const int* __restrict__ eidx,
    const int* __restrict__ sidx, const int* __restrict__ seq_len,
    int E, int B) {
    extern __shared__ unsigned char smraw[];
    SmemM* S = (SmemM*)smraw;
    int b = blockIdx.x, tid = threadIdx.x;
    int nbase = g_node_off[b];
    int nn = g_node_off[b + 1] - nbase;
    int eps = E / B;
    int ne = eps + nn;
    int tbase = g_tok_off[b];
    int sl = seq_len[b];

    if (tid < NN) { S->deg[tid] = 0; S->cnt[tid] = 0; }
    // zero A region (R)
    for (int i = tid; i < NN * 48; i += NTHREADS) S->R[i] = 0.f;
    // load X
    {
        const float4* src = (const float4*)(hidden + (size_t)nbase * Dq);
        float4* dst = (float4*)S->X;
        int cnt4 = nn * (Dq / 4);
        for (int i = tid; i < cnt4; i += NTHREADS) dst[i] = src[i];
        for (int i = nn * Dq + tid; i < NN * Dq; i += NTHREADS) S->X[i] = 0.f;
    }
    // edges + self loops
    for (int e = tid; e < ne; e += NTHREADS) {
        int s, d;
        if (e < eps) {
            s = eidx[(size_t)b * eps + e] - nbase;
            d = eidx[(size_t)E + (size_t)b * eps + e] - nbase;
        } else {
            s = d = e - eps;
        }
        S->es[e] = s; S->ed[e] = d;
    }
    if (tid == 0) S->lastnode = sidx[tbase + sl - 1];
    __syncthreads();
    for (int e = tid; e < ne; e += NTHREADS) atomicAdd(&S->deg[S->ed[e]], 1);
    for (int t = tid; t < sl; t += NTHREADS) atomicAdd(&S->cnt[sidx[tbase + t]], 1);
    __syncthreads();
    if (tid < nn) S->dinv[tid] = rsqrtf((float)S->deg[tid]);
    __syncthreads();
    for (int e = tid; e < ne; e += NTHREADS)
        S->ew[e] = S->dinv[S->es[e]] * S->dinv[S->ed[e]];
    if (tid == 32) {
        int ln = S->lastnode;
        int na = 0, jl = 0;
        for (int n2 = 0; n2 < nn; n2++)
            if (S->cnt[n2] > 0) {
                if (n2 == ln) jl = na;
                S->act[na++] = n2;
            }
        S->nact = na;
        S->jlast = jl;
    }
    __syncthreads();
    // build dense A (deterministic per-target scan); A = R region
    if (tid < nn) {
        float* Arow = S->R + tid * 48;
        for (int e = 0; e < ne; e++)
            if (S->ed[e] == tid) Arow[S->es[e]] += S->ew[e];
    }
    __syncthreads();
    int nact = S->nact;
    // A2act[j][rc] = sum_r A[act_j][r] * A[r][rc]
    for (int c = tid; c < nact * NN; c += NTHREADS) {
        int j = c / NN, rc = c - j * NN;
        const float* Aj = S->R + S->act[j] * 48;
        float s = 0.f;
        for (int r = 0; r < NN; r++) s += Aj[r] * S->R[r * 48 + rc];
        S->A2[j * 48 + rc] = s;
    }
    __syncthreads();
    // z = A2act[jlast] @ X  (per-k threads)
    {
        int jl = S->jlast;
        float s = 0.f;
        const float* a2 = S->A2 + jl * 48;
#pragma unroll 8
        for (int r = 0; r < NN; r++) s += a2[r] * S->X[r * Dq + tid];
        S->z[tid] = s;
    }
    __syncthreads();
    // u[h] = c[h] + z @ M1[:,h]   (64 h x 8 k-slices, partials in R)
    {
        int h = tid & 63, k8 = tid >> 6;
        const float* m1 = g_M1 + (k8 * 64) * Hq + h;
        const float* zz = S->z + k8 * 64;
        float s = 0.f;
#pragma unroll 8
        for (int kk = 0; kk < 64; kk++) s += zz[kk] * m1[kk * Hq];
        S->R[k8 * 64 + h] = s;
    }
    __syncthreads();
    if (tid < Hq) {
        float s = g_c[tid];
#pragma unroll
        for (int k8 = 0; k8 < 8; k8++) s += S->R[k8 * 64 + tid];
        S->u[tid] = s;
    }
    __syncthreads();

    // ---- GEMM: Y = X @ M2  (tile: 16 h-quads x 8 j-groups(5 rows) x 4 k-slices) ----
    {
        int h4 = tid & 15, jg = (tid >> 4) & 7, ks = tid >> 7;
        int lh = h4 * 4;
        int r0 = jg * 5;
        int lk = tid >> 4;  // 0..31 stage row
        float* st = S->R;
        ull acc[5][2];
#pragma unroll
        for (int i = 0; i < 5; i++) { acc[i][0] = 0ull; acc[i][1] = 0ull; }
        float4 pf = *(const float4*)(g_M2 + lk * Hq + lh);
        for (int ch = 0; ch < 16; ch++) {
            *(float4*)(st + lk * 68 + lh) = pf;
            __syncthreads();
            if (ch < 15) pf = *(const float4*)(g_M2 + ((ch + 1) * 32 + lk) * Hq + lh);
            int kb = ks * 8;
#pragma unroll
            for (int q = 0; q < 2; q++) {
                int kk0 = kb + q * 4;
                int kg = ch * 32 + kk0;
                float4 xv[5];
#pragma unroll
                for (int i = 0; i < 5; i++)
                    xv[i] = *(const float4*)(S->X + (r0 + i) * Dq + kg);
#pragma unroll
                for (int kk = 0; kk < 4; kk++) {
                    const ull* mp = (const ull*)(st + (kk0 + kk) * 68 + lh);
                    ull m01 = mp[0], m23 = mp[1];
#pragma unroll
                    for (int i = 0; i < 5; i++) {
                        float xs = (kk == 0) ? xv[i].x : (kk == 1) ? xv[i].y
                                 : (kk == 2) ? xv[i].z : xv[i].w;
                        ull xp = splat2(xs);
                        ffma2(acc[i][0], xp, m01);
                        ffma2(acc[i][1], xp, m23);
                    }
                }
            }
            __syncthreads();
        }
        // reduce over ks into Y (4 deterministic rounds)
        for (int r = 0; r < 4; r++) {
            if (ks == r) {
#pragma unroll
                for (int i = 0; i < 5; i++)
#pragma unroll
                    for (int p = 0; p < 2; p++) {
                        float2 v = unpk(acc[i][p]);
                        float2* yp = (float2*)(S->Y + (r0 + i) * Hq + lh + 2 * p);
                        if (r == 0) *yp = v;
                        else { float2 o = *yp; o.x += v.x; o.y += v.y; *yp = o; }
                    }
            }
            __syncthreads();
        }
    }

    // ---- alpha per active node ----
    {
        int lane = tid & 31, wp = tid >> 5;
        float bq0 = bq[0];
        float wql = Wq[lane], wqh = Wq[lane + 32];
        float ul = S->u[lane], uh = S->u[lane + 32];
        for (int j = wp; j < nact; j += 16) {
            const float* a2 = S->A2 + j * 48;
            float x1 = ul, x2 = uh;
#pragma unroll 8
            for (int r = 0; r < NN; r++) {
                float av = a2[r];
                x1 += av * S->Y[r * Hq + lane];
                x2 += av * S->Y[r * Hq + lane + 32];
            }
            float s = wql / (1.f + __expf(-x1)) + wqh / (1.f + __expf(-x2));
            for (int o = 16; o; o >>= 1) s += __shfl_xor_sync(0xffffffffu, s, o);
            if (lane == 0) S->af[j] = (s + bq0) * (float)S->cnt[S->act[j]];
        }
    }
    __syncthreads();
    if (tid == 0) {
        float A = 0.f;
        for (int j = 0; j < nact; j++) A += S->af[j];
        g_A[b] = A;
    }
    // w[r] = sum_j af[j] * A2act[j][r]
    if (tid < NN) {
        float s = 0.f;
        for (int j = 0; j < nact; j++) s += S->af[j] * S->A2[j * 48 + tid];
        S->w[tid] = s;
    }
    __syncthreads();
    // sP[k] = sum_r w[r] * X[r][k] ; write VS
    {
        float s = 0.f;
#pragma unroll 8
        for (int r = 0; r < NN; r++) s += S->w[r] * S->X[r * Dq + tid];
        g_VS[(size_t)b * 1024 + tid] = S->z[tid];
        g_VS[(size_t)b * 1024 + 512 + tid] = s;
    }
}

// ---------------- final matvec: out = VS @ M3 + d3 + A*e3 ----------------
#define FB 16
#define MS 132
__global__ void __launch_bounds__(256) k_final(float* __restrict__ out, int B) {
    extern __shared__ float fsm[];
    float* vs = fsm;               // FB * 1024
    float* mch = fsm + FB * 1024;  // 64 * MS
    int sb = blockIdx.x * FB;
    int tid = threadIdx.x;
    {
        const float4* src = (const float4*)(g_VS + (size_t)sb * 1024);
        float4* dst = (float4*)vs;
        for (int i = tid; i < FB * 256; i += 256) dst[i] = src[i];
    }
    int h = tid & 63, sg = tid >> 6;
    float acc[4] = {0.f, 0.f, 0.f, 0.f};
    const float* vsr0 = vs + (sg * 4 + 0) * 1024;
    const float* vsr1 = vs + (sg * 4 + 1) * 1024;
    const float* vsr2 = vs + (sg * 4 + 2) * 1024;
    const float* vsr3 = vs + (sg * 4 + 3) * 1024;
    for (int kc = 0; kc < 1024; kc += 128) {
        __syncthreads();
        for (int i = tid; i < 64 * 32; i += 256) {
            int r = i >> 5, c = i & 31;
            float4 v = *(const float4*)(g_M3T + r * 1040 + kc + c * 4);
            *(float4*)(mch + r * MS + c * 4) = v;
        }
        __syncthreads();
#pragma unroll 8
        for (int kk = 0; kk < 128; kk += 4) {
            float4 m = *(const float4*)(mch + h * MS + kk);
            float4 a0 = *(const float4*)(vsr0 + kc + kk);
            float4 a1 = *(const float4*)(vsr1 + kc + kk);
            float4 a2 = *(const float4*)(vsr2 + kc + kk);
            float4 a3 = *(const float4*)(vsr3 + kc + kk);
            acc[0] += a0.x * m.x + a0.y * m.y + a0.z * m.z + a0.w * m.w;
            acc[1] += a1.x * m.x + a1.y * m.y + a1.z * m.z + a1.w * m.w;
            acc[2] += a2.x * m.x + a2.y * m.y + a2.z * m.z + a2.w * m.w;
            acc[3] += a3.x * m.x + a3.y * m.y + a3.z * m.z + a3.w * m.w;
        }
    }
    float d3 = g_d3[h], e3 = g_e3[h];
#pragma unroll
    for (int i = 0; i < 4; i++) {
        int b = sb + sg * 4 + i;
        if (b < B) out[(size_t)b * Hq + h] = acc[i] + d3 + g_A[b] * e3;
    }
}

// ---------------- launch ----------------
extern "C" void kernel_launch(void* const* d_in, const int* in_sizes, int n_in,
                              void* d_out, int out_size) {
    const float* hidden = (const float*)d_in[0];
    const float* Wg = (const float*)d_in[1];
    const float* bg = (const float*)d_in[2];
    const float* W1 = (const float*)d_in[3];
    const float* b1 = (const float*)d_in[4];
    const float* W2 = (const float*)d_in[5];
    const float* b2 = (const float*)d_in[6];
    const float* Wq = (const float*)d_in[7];
    const float* bq = (const float*)d_in[8];
    const float* W3 = (const float*)d_in[9];
    const float* b3 = (const float*)d_in[10];
    const int* eidx = (const int*)d_in[11];
    const int* batch = (const int*)d_in[12];
    const int* sidx = (const int*)d_in[13];
    const int* seql = (const int*)d_in[14];

    int N = in_sizes[0] / Dq;
    int B = in_sizes[14];
    int E = in_sizes[11] / 2;
    float* out = (float*)d_out;

    k_mark<<<(N + 255) / 256, 256>>>(batch, N);
    k_scan<<<1, 1024>>>(seql, B, N);
    dim3 gm(Dq / 8, 4);
    k_mats<<<gm, 256>>>(Wg, W1, W2, W3);
    k_vecs<<<Hq, 128>>>(bg, b1, b2, b3, W1, W2, W3);

    cudaFuncSetAttribute(k_main, cudaFuncAttributeMaxDynamicSharedMemorySize,
                         (int)sizeof(SmemM));
    k_main<<<B, NTHREADS, sizeof(SmemM)>>>(hidden, Wq, bq, eidx, sidx, seql, E, B);

    int fsmem = (FB * 1024 + 64 * MS) * (int)sizeof(float);
    cudaFuncSetAttribute(k_final, cudaFuncAttributeMaxDynamicSharedMemorySize, fsmem);
    k_final<<<(B + FB - 1) / FB, 256, fsmem>>>(out, B);
}